// round 9
// baseline (speedup 1.0000x reference)
#include <cuda_runtime.h>
#include <math.h>

// Fixed shapes (from reference setup_inputs)
#define D_IN    4096
#define D_OUT   4096
#define NROWS   8192          // B*S
#define RANK    8
#define SCALING 2.0f          // ALPHA/RANK
#define EPS     1e-8f
#define NC4     (D_IN / 4)    // 1024 float4 columns per row

// rowdot grid: 12288 data rows + 8 A rows, 2 rows per block
#define RD_ROWS_PB   2
#define RD_DATA_BLK  ((D_OUT + NROWS) / RD_ROWS_PB)    // 6144
#define RD_GRID      (RD_DATA_BLK + RANK / RD_ROWS_PB) // 6148

// Scratch (allocation-free: __device__ globals)
__device__ float g_w2[D_OUT];            // ||bw_row||^2
__device__ float g_wA[D_OUT * RANK];     // bw @ A^T
__device__ float g_lxr[NROWS * RANK];    // x @ A^T
__device__ float g_G[RANK * RANK];       // A @ A^T

__device__ __forceinline__ float dot4(float4 a, float4 b) {
    return a.x * b.x + a.y * b.y + a.z * b.z + a.w * b.w;
}

// ---------------------------------------------------------------------------
// rowdot: one pass over {bw rows, x rows, A rows}; for each row s computes
// s . A_r (r=0..7) and ||s||^2.  2 rows/block, fully unrolled column loop
// with all 8 row-loads front-batched (MLP=8/thread).  A via __ldg stays
// L1-resident across sequential CTAs; streamed rows use .cs (evict-first).
// ---------------------------------------------------------------------------
__global__ __launch_bounds__(256, 3)
void rowdot_kernel(const float* __restrict__ bw,
                   const float* __restrict__ x,
                   const float* __restrict__ A)
{
    const int tid   = threadIdx.x;
    const int grow0 = blockIdx.x * RD_ROWS_PB;   // 0..12294
    const float4* __restrict__ A4 = (const float4*)A;

    const float* __restrict__ src;
    if (grow0 < D_OUT)                 src = bw + (size_t)grow0 * D_IN;
    else if (grow0 < D_OUT + NROWS)    src = x  + (size_t)(grow0 - D_OUT) * D_IN;
    else                               src = A  + (size_t)(grow0 - D_OUT - NROWS) * D_IN;

    // front-batch all 8 row loads (4 column chunks x 2 rows)
    float4 v[4][RD_ROWS_PB];
#pragma unroll
    for (int i = 0; i < 4; i++)
#pragma unroll
        for (int n = 0; n < RD_ROWS_PB; n++)
            v[i][n] = __ldcs(((const float4*)(src + (size_t)n * D_IN)) + tid + i * 256);

    float acc[RD_ROWS_PB][RANK];
    float sq[RD_ROWS_PB];
#pragma unroll
    for (int n = 0; n < RD_ROWS_PB; n++) {
        sq[n] = 0.f;
#pragma unroll
        for (int r = 0; r < RANK; r++) acc[n][r] = 0.f;
    }

#pragma unroll
    for (int i = 0; i < 4; i++) {
#pragma unroll
        for (int r = 0; r < RANK; r++) {
            float4 a = __ldg(&A4[r * NC4 + tid + i * 256]);
#pragma unroll
            for (int n = 0; n < RD_ROWS_PB; n++)
                acc[n][r] += dot4(v[i][n], a);
        }
#pragma unroll
        for (int n = 0; n < RD_ROWS_PB; n++)
            sq[n] += dot4(v[i][n], v[i][n]);
    }

    // reduce 2*(8+1) = 18 values: warp shuffle then cross-warp
#pragma unroll
    for (int n = 0; n < RD_ROWS_PB; n++) {
#pragma unroll
        for (int r = 0; r < RANK; r++)
#pragma unroll
            for (int off = 16; off; off >>= 1)
                acc[n][r] += __shfl_xor_sync(0xffffffffu, acc[n][r], off);
#pragma unroll
        for (int off = 16; off; off >>= 1)
            sq[n] += __shfl_xor_sync(0xffffffffu, sq[n], off);
    }

    __shared__ float red[8][18];
    const int warp = tid >> 5, lane = tid & 31;
    if (lane == 0) {
#pragma unroll
        for (int n = 0; n < RD_ROWS_PB; n++) {
#pragma unroll
            for (int r = 0; r < RANK; r++) red[warp][n * 9 + r] = acc[n][r];
            red[warp][n * 9 + 8] = sq[n];
        }
    }
    __syncthreads();

    if (tid < 18) {
        float s = 0.f;
#pragma unroll
        for (int w = 0; w < 8; w++) s += red[w][tid];
        const int n = tid / 9, k = tid % 9;
        const int grow = grow0 + n;
        if (grow < D_OUT) {
            if (k < 8) g_wA[grow * RANK + k] = s;
            else       g_w2[grow] = s;
        } else if (grow < D_OUT + NROWS) {
            if (k < 8) g_lxr[(grow - D_OUT) * RANK + k] = s;
        } else {
            if (k < 8) g_G[(grow - D_OUT - NROWS) * RANK + k] = s;
        }
    }
}

// ---------------------------------------------------------------------------
// out: prologue recomputes (per block, redundantly but cheaply)
//   n2[o]  = w2[o] + 2s*B_o.wA[o] + s^2 * B_o^T G B_o
//   ms[o]  = mag[o] / (sqrt(n2)+eps),   Bs[o,r] = B[o,r]*s*ms[o]
// then streams: out[s,o] = bo[s,o]*ms[o] + dot(lxr[s,:], Bs[o,:])
// 64 rows x 1024 cols per block; 8-deep row-load batches (MLP=8).
// ---------------------------------------------------------------------------
__global__ __launch_bounds__(256, 3)
void out_kernel(const float* __restrict__ bo,
                float* __restrict__ out,
                const float* __restrict__ Bm,
                const float* __restrict__ mag)
{
    __shared__ float Gs[RANK * RANK];
    __shared__ float lxs[64 * RANK];            // 512 floats
    const int tid  = threadIdx.x;
    const int row0 = blockIdx.y * 64;
    const int c4g  = blockIdx.x * 256 + tid;    // global float4 column

    if (tid < RANK * RANK) Gs[tid] = g_G[tid];
    lxs[tid]       = g_lxr[row0 * RANK + tid];
    lxs[tid + 256] = g_lxr[row0 * RANK + 256 + tid];
    __syncthreads();

    const float4 w2v  = __ldg(&((const float4*)g_w2)[c4g]);
    const float4 magv = __ldg(&((const float4*)mag)[c4g]);
    const float w2a[4]  = { w2v.x, w2v.y, w2v.z, w2v.w };
    const float maga[4] = { magv.x, magv.y, magv.z, magv.w };

    float ms[4];
    float Bsf[32];                              // Bsf[k*8+r] = Bs[col k][r]
#pragma unroll
    for (int k = 0; k < 4; k++) {
        const int col = c4g * 4 + k;
        float4 b0 = __ldg(&((const float4*)Bm)[col * 2 + 0]);
        float4 b1 = __ldg(&((const float4*)Bm)[col * 2 + 1]);
        float4 w0 = __ldg(&((const float4*)g_wA)[col * 2 + 0]);
        float4 w1 = __ldg(&((const float4*)g_wA)[col * 2 + 1]);
        float B[8]  = { b0.x, b0.y, b0.z, b0.w, b1.x, b1.y, b1.z, b1.w };
        float wA[8] = { w0.x, w0.y, w0.z, w0.w, w1.x, w1.y, w1.z, w1.w };

        float lin = 0.f, quad = 0.f;
#pragma unroll
        for (int r = 0; r < RANK; r++) {
            lin += B[r] * wA[r];
            float t = 0.f;
#pragma unroll
            for (int r2 = 0; r2 < RANK; r2++)
                t += Gs[r * RANK + r2] * B[r2];
            quad += B[r] * t;
        }
        float n2 = w2a[k] + 2.f * SCALING * lin + SCALING * SCALING * quad;
        float m  = maga[k] / (sqrtf(n2) + EPS);
        ms[k] = m;
        float sc = SCALING * m;
#pragma unroll
        for (int r = 0; r < RANK; r++)
            Bsf[k * 8 + r] = B[r] * sc;
    }

    // main stream: 8 groups of 8 rows, loads batched for MLP=8
#pragma unroll 1
    for (int rb = 0; rb < 8; rb++) {
        float4 b[8];
#pragma unroll
        for (int j = 0; j < 8; j++) {
            const int row = row0 + rb * 8 + j;
            b[j] = __ldcs(&((const float4*)(bo + (size_t)row * D_OUT))[c4g]);
        }
#pragma unroll
        for (int j = 0; j < 8; j++) {
            const int rl = rb * 8 + j;
            const float* lx = &lxs[rl * RANK];

            float o0 = b[j].x * ms[0];
            float o1 = b[j].y * ms[1];
            float o2 = b[j].z * ms[2];
            float o3 = b[j].w * ms[3];
#pragma unroll
            for (int r = 0; r < RANK; r++) {
                const float l = lx[r];
                o0 += l * Bsf[0 * 8 + r];
                o1 += l * Bsf[1 * 8 + r];
                o2 += l * Bsf[2 * 8 + r];
                o3 += l * Bsf[3 * 8 + r];
            }
            __stcs(&((float4*)(out + (size_t)(row0 + rl) * D_OUT))[c4g],
                   make_float4(o0, o1, o2, o3));
        }
    }
}

// ---------------------------------------------------------------------------
extern "C" void kernel_launch(void* const* d_in, const int* in_sizes, int n_in,
                              void* d_out, int out_size)
{
    const float* x   = (const float*)d_in[0];   // [8192, 4096]
    const float* bo  = (const float*)d_in[1];   // [8192, 4096]
    const float* bw  = (const float*)d_in[2];   // [4096, 4096]
    const float* A   = (const float*)d_in[3];   // [8, 4096]
    const float* Bm  = (const float*)d_in[4];   // [4096, 8]
    const float* mag = (const float*)d_in[5];   // [4096]
    float* out = (float*)d_out;                 // [8192, 4096]

    rowdot_kernel<<<RD_GRID, 256>>>(bw, x, A);
    dim3 g2(D_OUT / 1024, NROWS / 64);
    out_kernel<<<g2, 256>>>(bo, out, Bm, mag);
}

// round 12
// speedup vs baseline: 1.0051x; 1.0051x over previous
#include <cuda_runtime.h>
#include <math.h>

// Fixed shapes (from reference setup_inputs)
#define D_IN    4096
#define D_OUT   4096
#define NROWS   8192          // B*S
#define RANK    8
#define SCALING 2.0f          // ALPHA/RANK
#define EPS     1e-8f
#define NC4     (D_IN / 4)    // 1024 float4 columns per row

// rowdot grid: 12288 data rows + 8 A rows, 4 rows per block
#define RD_ROWS_PB   4
#define RD_GRID      ((D_OUT + NROWS + RANK) / RD_ROWS_PB)   // 3074

// Scratch (allocation-free: __device__ globals)
__device__ float g_w2[D_OUT];            // ||bw_row||^2
__device__ float g_wA[D_OUT * RANK];     // bw @ A^T
__device__ float g_lxr[NROWS * RANK];    // x @ A^T
__device__ float g_G[RANK * RANK];       // A @ A^T

__device__ __forceinline__ float dot4(float4 a, float4 b) {
    return a.x * b.x + a.y * b.y + a.z * b.z + a.w * b.w;
}

// ---------------------------------------------------------------------------
// rowdot: one pass over {bw rows, x rows, A rows}; for each row s computes
// s . A_r (r=0..7) and ||s||^2 (bw rows only).  4 rows/block, 4 CTAs/SM.
// A via __ldg (L1-persistent across CTAs); streamed rows via .cs.
// ---------------------------------------------------------------------------
__global__ __launch_bounds__(256, 4)
void rowdot_kernel(const float* __restrict__ bw,
                   const float* __restrict__ x,
                   const float* __restrict__ A)
{
    const int tid   = threadIdx.x;
    const int grow0 = blockIdx.x * RD_ROWS_PB;   // 0..12292
    const float4* __restrict__ A4 = (const float4*)A;

    const float* __restrict__ src;
    const bool is_bw = (grow0 < D_OUT);
    if (is_bw)                         src = bw + (size_t)grow0 * D_IN;
    else if (grow0 < D_OUT + NROWS)    src = x  + (size_t)(grow0 - D_OUT) * D_IN;
    else                               src = A  + (size_t)(grow0 - D_OUT - NROWS) * D_IN;

    float acc[RD_ROWS_PB][RANK];
    float sq[RD_ROWS_PB];
#pragma unroll
    for (int n = 0; n < RD_ROWS_PB; n++) {
        sq[n] = 0.f;
#pragma unroll
        for (int r = 0; r < RANK; r++) acc[n][r] = 0.f;
    }

#pragma unroll
    for (int i = 0; i < 4; i++) {
        const int c = tid + i * 256;
        float4 v[RD_ROWS_PB];
#pragma unroll
        for (int n = 0; n < RD_ROWS_PB; n++)
            v[n] = __ldcs(((const float4*)(src + (size_t)n * D_IN)) + c);

#pragma unroll
        for (int r = 0; r < RANK; r++) {
            float4 a = __ldg(&A4[r * NC4 + c]);
#pragma unroll
            for (int n = 0; n < RD_ROWS_PB; n++)
                acc[n][r] += dot4(v[n], a);
        }
        if (is_bw) {
#pragma unroll
            for (int n = 0; n < RD_ROWS_PB; n++)
                sq[n] += dot4(v[n], v[n]);
        }
    }

    // warp-level tree reduction, then cross-warp via shared
#pragma unroll
    for (int n = 0; n < RD_ROWS_PB; n++) {
#pragma unroll
        for (int r = 0; r < RANK; r++)
#pragma unroll
            for (int off = 16; off; off >>= 1)
                acc[n][r] += __shfl_xor_sync(0xffffffffu, acc[n][r], off);
#pragma unroll
        for (int off = 16; off; off >>= 1)
            sq[n] += __shfl_xor_sync(0xffffffffu, sq[n], off);
    }

    __shared__ float red[8][RD_ROWS_PB * 9];
    const int warp = tid >> 5, lane = tid & 31;
    if (lane == 0) {
#pragma unroll
        for (int n = 0; n < RD_ROWS_PB; n++) {
#pragma unroll
            for (int r = 0; r < RANK; r++) red[warp][n * 9 + r] = acc[n][r];
            red[warp][n * 9 + 8] = sq[n];
        }
    }
    __syncthreads();

    if (tid < RD_ROWS_PB * 9) {
        float s = 0.f;
#pragma unroll
        for (int w = 0; w < 8; w++) s += red[w][tid];
        const int n = tid / 9, k = tid % 9;
        const int grow = grow0 + n;
        if (grow < D_OUT) {
            if (k < 8) g_wA[grow * RANK + k] = s;
            else       g_w2[grow] = s;
        } else if (grow < D_OUT + NROWS) {
            if (k < 8) g_lxr[(grow - D_OUT) * RANK + k] = s;
        } else {
            if (k < 8) g_G[(grow - D_OUT - NROWS) * RANK + k] = s;
        }
    }
}

// ---------------------------------------------------------------------------
// out: prologue recomputes per block (cheap, redundant)
//   n2[o] = w2[o] + 2s*B_o.wA[o] + s^2 * B_o^T G B_o
//   ms[o] = mag[o]/(sqrt(n2)+eps),   Bs[o,r] = B[o,r]*s*ms[o]
// then streams: out[s,o] = bo[s,o]*ms[o] + dot(lxr[s,:], Bs[o,:])
// 32 rows x 1024 cols per block (grid 1024), 4-deep row-load batches,
// 4 CTAs/SM.
// ---------------------------------------------------------------------------
__global__ __launch_bounds__(256, 4)
void out_kernel(const float* __restrict__ bo,
                float* __restrict__ out,
                const float* __restrict__ Bm,
                const float* __restrict__ mag)
{
    __shared__ float Gs[RANK * RANK];
    __shared__ float lxs[32 * RANK];            // 256 floats
    const int tid  = threadIdx.x;
    const int row0 = blockIdx.y * 32;
    const int c4g  = blockIdx.x * 256 + tid;    // global float4 column

    if (tid < RANK * RANK) Gs[tid] = g_G[tid];
    lxs[tid] = g_lxr[row0 * RANK + tid];
    __syncthreads();

    const float4 w2v  = __ldg(&((const float4*)g_w2)[c4g]);
    const float4 magv = __ldg(&((const float4*)mag)[c4g]);
    const float w2a[4]  = { w2v.x, w2v.y, w2v.z, w2v.w };
    const float maga[4] = { magv.x, magv.y, magv.z, magv.w };

    float ms[4];
    float Bsf[32];                              // Bsf[k*8+r] = Bs[col k][r]
#pragma unroll
    for (int k = 0; k < 4; k++) {
        const int col = c4g * 4 + k;
        float4 b0 = __ldg(&((const float4*)Bm)[col * 2 + 0]);
        float4 b1 = __ldg(&((const float4*)Bm)[col * 2 + 1]);
        float4 w0 = __ldg(&((const float4*)g_wA)[col * 2 + 0]);
        float4 w1 = __ldg(&((const float4*)g_wA)[col * 2 + 1]);
        float B[8]  = { b0.x, b0.y, b0.z, b0.w, b1.x, b1.y, b1.z, b1.w };
        float wA[8] = { w0.x, w0.y, w0.z, w0.w, w1.x, w1.y, w1.z, w1.w };

        float lin = 0.f, quad = 0.f;
#pragma unroll
        for (int r = 0; r < RANK; r++) {
            lin += B[r] * wA[r];
            float t = 0.f;
#pragma unroll
            for (int r2 = 0; r2 < RANK; r2++)
                t += Gs[r * RANK + r2] * B[r2];
            quad += B[r] * t;
        }
        float n2 = w2a[k] + 2.f * SCALING * lin + SCALING * SCALING * quad;
        float m  = maga[k] / (sqrtf(n2) + EPS);
        ms[k] = m;
        float sc = SCALING * m;
#pragma unroll
        for (int r = 0; r < RANK; r++)
            Bsf[k * 8 + r] = B[r] * sc;
    }

    // main stream: 8 groups of 4 rows, loads batched (MLP=4/thread)
#pragma unroll 1
    for (int rb = 0; rb < 8; rb++) {
        float4 b[4];
#pragma unroll
        for (int j = 0; j < 4; j++) {
            const int row = row0 + rb * 4 + j;
            b[j] = __ldcs(&((const float4*)(bo + (size_t)row * D_OUT))[c4g]);
        }
#pragma unroll
        for (int j = 0; j < 4; j++) {
            const int rl = rb * 4 + j;
            const float* lx = &lxs[rl * RANK];

            float o0 = b[j].x * ms[0];
            float o1 = b[j].y * ms[1];
            float o2 = b[j].z * ms[2];
            float o3 = b[j].w * ms[3];
#pragma unroll
            for (int r = 0; r < RANK; r++) {
                const float l = lx[r];
                o0 += l * Bsf[0 * 8 + r];
                o1 += l * Bsf[1 * 8 + r];
                o2 += l * Bsf[2 * 8 + r];
                o3 += l * Bsf[3 * 8 + r];
            }
            __stcs(&((float4*)(out + (size_t)(row0 + rl) * D_OUT))[c4g],
                   make_float4(o0, o1, o2, o3));
        }
    }
}

// ---------------------------------------------------------------------------
extern "C" void kernel_launch(void* const* d_in, const int* in_sizes, int n_in,
                              void* d_out, int out_size)
{
    const float* x   = (const float*)d_in[0];   // [8192, 4096]
    const float* bo  = (const float*)d_in[1];   // [8192, 4096]
    const float* bw  = (const float*)d_in[2];   // [4096, 4096]
    const float* A   = (const float*)d_in[3];   // [8, 4096]
    const float* Bm  = (const float*)d_in[4];   // [4096, 8]
    const float* mag = (const float*)d_in[5];   // [4096]
    float* out = (float*)d_out;                 // [8192, 4096]

    rowdot_kernel<<<RD_GRID, 256>>>(bw, x, A);
    dim3 g2(D_OUT / 1024, NROWS / 32);
    out_kernel<<<g2, 256>>>(bo, out, Bm, mag);
}